// round 1
// baseline (speedup 1.0000x reference)
#include <cuda_runtime.h>
#include <math.h>

// ---------------- problem constants ----------------
#define BB 16
#define HH 64
#define WW 64
#define CC 192
#define HD 32
#define NH 6
#define PP 8
#define SH 4          // SHIFT
#define NW 64         // (H/P)*(W/P)
#define TOK (BB*HH*WW)        // 65536 tokens
#define PPW 64        // tokens per window (P*P)

// ---------------- scratch (device globals; no allocation) ----------------
__device__ float g_hwin[TOK * CC];        // LN1 + roll + window-partitioned
__device__ float g_qkv [TOK * 3 * CC];    // qkv
__device__ float g_attn[TOK * CC];        // attention output (windowed layout)
__device__ float g_x1  [TOK * CC];        // x + proj (image layout)
__device__ float g_h2  [TOK * CC];        // LN2 output
__device__ float g_hid [TOK * 4 * CC];    // mlp hidden

// ---------------- LN1 + roll(-4,-4) + window partition ----------------
// one warp per output (windowed) token
__global__ void ln1_window_kernel(const float* __restrict__ x,
                                  const float* __restrict__ g,
                                  const float* __restrict__ b) {
    int warp = threadIdx.x >> 5;
    int lane = threadIdx.x & 31;
    int token = blockIdx.x * 8 + warp;          // windowed token index
    int b_  = token >> 12;                      // / 4096
    int rem = token & 4095;
    int wn  = rem >> 6;
    int t   = rem & 63;
    int y  = (((wn >> 3) << 3) + (t >> 3) + SH) & (HH - 1);
    int xx = (((wn & 7)  << 3) + (t & 7)  + SH) & (WW - 1);
    const float* src = x + (((size_t)b_ * HH + y) * WW + xx) * CC;

    float v[6];
    float s = 0.f;
    #pragma unroll
    for (int i = 0; i < 6; i++) { v[i] = src[lane + 32 * i]; s += v[i]; }
    #pragma unroll
    for (int o = 16; o; o >>= 1) s += __shfl_xor_sync(0xffffffffu, s, o);
    float mu = s * (1.f / CC);
    float s2 = 0.f;
    #pragma unroll
    for (int i = 0; i < 6; i++) { float d = v[i] - mu; s2 += d * d; }
    #pragma unroll
    for (int o = 16; o; o >>= 1) s2 += __shfl_xor_sync(0xffffffffu, s2, o);
    float inv = rsqrtf(s2 * (1.f / CC) + 1e-5f);

    float* dst = g_hwin + (size_t)token * CC;
    #pragma unroll
    for (int i = 0; i < 6; i++) {
        int c = lane + 32 * i;
        dst[c] = (v[i] - mu) * inv * g[c] + b[c];
    }
}

// ---------------- LN2 (plain, image layout) ----------------
__global__ void ln2_kernel(const float* __restrict__ g,
                           const float* __restrict__ b) {
    int warp = threadIdx.x >> 5;
    int lane = threadIdx.x & 31;
    int token = blockIdx.x * 8 + warp;
    const float* src = g_x1 + (size_t)token * CC;
    float v[6];
    float s = 0.f;
    #pragma unroll
    for (int i = 0; i < 6; i++) { v[i] = src[lane + 32 * i]; s += v[i]; }
    #pragma unroll
    for (int o = 16; o; o >>= 1) s += __shfl_xor_sync(0xffffffffu, s, o);
    float mu = s * (1.f / CC);
    float s2 = 0.f;
    #pragma unroll
    for (int i = 0; i < 6; i++) { float d = v[i] - mu; s2 += d * d; }
    #pragma unroll
    for (int o = 16; o; o >>= 1) s2 += __shfl_xor_sync(0xffffffffu, s2, o);
    float inv = rsqrtf(s2 * (1.f / CC) + 1e-5f);
    float* dst = g_h2 + (size_t)token * CC;
    #pragma unroll
    for (int i = 0; i < 6; i++) {
        int c = lane + 32 * i;
        dst[c] = (v[i] - mu) * inv * g[c] + b[c];
    }
}

// ---------------- attention: one block per (batch, window, head) ----------------
__global__ __launch_bounds__(256)
void attn_kernel(const float* __restrict__ rel_pos) {
    __shared__ float qs[64][36];
    __shared__ float ks[64][36];
    __shared__ float vs[64][36];
    __shared__ float sc[64][65];

    int bid  = blockIdx.x;
    int head = bid % NH;
    int wnb  = bid / NH;
    int wn   = wnb % NW;
    int b_   = wnb / NW;
    int tokbase = (b_ * NW + wn) * PPW;
    bool lastRow = (wn >> 3) == 7;
    bool lastCol = (wn & 7) == 7;

    int tid = threadIdx.x;
    // load q/k/v tiles (64 x 32 each)
    const float* qbase = g_qkv + (size_t)tokbase * 576 + head * HD;
    #pragma unroll
    for (int i = 0; i < 8; i++) {
        int e = tid + 256 * i;      // 0..2047
        int p = e >> 5, d = e & 31;
        const float* tp = qbase + (size_t)p * 576 + d;
        qs[p][d] = tp[0];
        ks[p][d] = tp[192];
        vs[p][d] = tp[384];
    }
    __syncthreads();

    // scores: each thread: one query row p, 16 key columns
    {
        int p  = tid >> 2;
        int jb = (tid & 3) * 16;
        float4 q0 = *(const float4*)&qs[p][0];
        float4 q1 = *(const float4*)&qs[p][4];
        float4 q2 = *(const float4*)&qs[p][8];
        float4 q3 = *(const float4*)&qs[p][12];
        float4 q4 = *(const float4*)&qs[p][16];
        float4 q5 = *(const float4*)&qs[p][20];
        float4 q6 = *(const float4*)&qs[p][24];
        float4 q7 = *(const float4*)&qs[p][28];
        int pi = p >> 3, pj = p & 7;
        const float* rp = rel_pos + head * 225;
        #pragma unroll
        for (int j = 0; j < 16; j++) {
            int qq = jb + j;
            const float* kr = &ks[qq][0];
            float4 k0 = *(const float4*)(kr + 0);
            float4 k1 = *(const float4*)(kr + 4);
            float4 k2 = *(const float4*)(kr + 8);
            float4 k3 = *(const float4*)(kr + 12);
            float4 k4 = *(const float4*)(kr + 16);
            float4 k5 = *(const float4*)(kr + 20);
            float4 k6 = *(const float4*)(kr + 24);
            float4 k7 = *(const float4*)(kr + 28);
            float s = q0.x*k0.x + q0.y*k0.y + q0.z*k0.z + q0.w*k0.w
                    + q1.x*k1.x + q1.y*k1.y + q1.z*k1.z + q1.w*k1.w
                    + q2.x*k2.x + q2.y*k2.y + q2.z*k2.z + q2.w*k2.w
                    + q3.x*k3.x + q3.y*k3.y + q3.z*k3.z + q3.w*k3.w
                    + q4.x*k4.x + q4.y*k4.y + q4.z*k4.z + q4.w*k4.w
                    + q5.x*k5.x + q5.y*k5.y + q5.z*k5.z + q5.w*k5.w
                    + q6.x*k6.x + q6.y*k6.y + q6.z*k6.z + q6.w*k6.w
                    + q7.x*k7.x + q7.y*k7.y + q7.z*k7.z + q7.w*k7.w;
            int qi = qq >> 3, qj = qq & 7;
            float bias = rp[(pi - qi + 7) * 15 + (pj - qj + 7)];
            s = s * 0.17677669529663687f + bias;   // 1/sqrt(32)
            bool m = (lastRow && ((pi < SH) != (qi < SH))) ||
                     (lastCol && ((pj < SH) != (qj < SH)));
            sc[p][qq] = m ? -INFINITY : s;
        }
    }
    __syncthreads();

    // softmax: each warp handles 8 rows
    {
        int warp = tid >> 5, lane = tid & 31;
        #pragma unroll
        for (int rr = 0; rr < 8; rr++) {
            int r = warp * 8 + rr;
            float a = sc[r][lane];
            float c = sc[r][lane + 32];
            float mx = fmaxf(a, c);
            #pragma unroll
            for (int o = 16; o; o >>= 1) mx = fmaxf(mx, __shfl_xor_sync(0xffffffffu, mx, o));
            float e1 = __expf(a - mx);
            float e2 = __expf(c - mx);
            float sm = e1 + e2;
            #pragma unroll
            for (int o = 16; o; o >>= 1) sm += __shfl_xor_sync(0xffffffffu, sm, o);
            float invs = 1.f / sm;
            sc[r][lane]      = e1 * invs;
            sc[r][lane + 32] = e2 * invs;
        }
    }
    __syncthreads();

    // PV: thread -> (p, 8 d's)
    {
        int p  = tid >> 2;
        int db = (tid & 3) * 8;
        float4 a0 = make_float4(0,0,0,0), a1 = make_float4(0,0,0,0);
        #pragma unroll 4
        for (int q = 0; q < 64; q++) {
            float pr = sc[p][q];
            float4 v0 = *(const float4*)&vs[q][db];
            float4 v1 = *(const float4*)&vs[q][db + 4];
            a0.x += pr * v0.x; a0.y += pr * v0.y; a0.z += pr * v0.z; a0.w += pr * v0.w;
            a1.x += pr * v1.x; a1.y += pr * v1.y; a1.z += pr * v1.z; a1.w += pr * v1.w;
        }
        float* dst = g_attn + (size_t)(tokbase + p) * CC + head * HD + db;
        *(float4*)(dst)     = a0;
        *(float4*)(dst + 4) = a1;
    }
}

// ---------------- tiled GEMM 64x64, BK=16, 4x4/thread ----------------
// MODE 0: out = acc + bias                           (qkv)
// MODE 1: remap windowed row -> pixel; out = res[pix] + acc + bias  (proj + unshift + residual)
// MODE 2: out = gelu(acc + bias)                     (mlp1)
// MODE 3: out = res[row] + acc + bias                (mlp2 + residual)
template <int MODE>
__global__ __launch_bounds__(256)
void gemm64_kernel(const float* __restrict__ A, const float* __restrict__ Bm,
                   const float* __restrict__ bias, float* __restrict__ Cout,
                   int N, int K, const float* __restrict__ res) {
    __shared__ float As[16][68];
    __shared__ float Bs[16][64];

    int tid = threadIdx.x;
    int bm = blockIdx.x * 64;
    int bn = blockIdx.y * 64;
    int ty = tid >> 4, tx = tid & 15;

    float acc[4][4] = {};

    int arow = tid >> 2;
    int acol = (tid & 3) * 4;
    int brow = tid >> 4;
    int bcol = (tid & 15) * 4;
    const float* Aptr = A + (size_t)(bm + arow) * K + acol;
    const float* Bptr = Bm + (size_t)brow * N + bn + bcol;

    for (int k0 = 0; k0 < K; k0 += 16) {
        float4 av = *(const float4*)(Aptr + k0);
        As[acol + 0][arow] = av.x;
        As[acol + 1][arow] = av.y;
        As[acol + 2][arow] = av.z;
        As[acol + 3][arow] = av.w;
        float4 bv = *(const float4*)(Bptr + (size_t)k0 * N);
        *(float4*)&Bs[brow][bcol] = bv;
        __syncthreads();
        #pragma unroll
        for (int k = 0; k < 16; k++) {
            float4 a  = *(const float4*)&As[k][ty * 4];
            float4 b4 = *(const float4*)&Bs[k][tx * 4];
            acc[0][0] += a.x * b4.x; acc[0][1] += a.x * b4.y; acc[0][2] += a.x * b4.z; acc[0][3] += a.x * b4.w;
            acc[1][0] += a.y * b4.x; acc[1][1] += a.y * b4.y; acc[1][2] += a.y * b4.z; acc[1][3] += a.y * b4.w;
            acc[2][0] += a.z * b4.x; acc[2][1] += a.z * b4.y; acc[2][2] += a.z * b4.z; acc[2][3] += a.z * b4.w;
            acc[3][0] += a.w * b4.x; acc[3][1] += a.w * b4.y; acc[3][2] += a.w * b4.z; acc[3][3] += a.w * b4.w;
        }
        __syncthreads();
    }

    int row0 = bm + ty * 4;
    int col0 = bn + tx * 4;
    float bv[4];
    #pragma unroll
    for (int j = 0; j < 4; j++) bv[j] = bias[col0 + j];

    #pragma unroll
    for (int i = 0; i < 4; i++) {
        int row = row0 + i;
        if (MODE == 1) {
            // windowed token row -> pixel index (un-window + roll(+4,+4))
            int b_  = row >> 12;
            int rem = row & 4095;
            int wn  = rem >> 6;
            int t   = rem & 63;
            int y  = (((wn >> 3) << 3) + (t >> 3) + SH) & (HH - 1);
            int xx = (((wn & 7)  << 3) + (t & 7)  + SH) & (WW - 1);
            size_t base = (size_t)(((b_ << 6) + y) * 64 + xx) * CC;
            #pragma unroll
            for (int j = 0; j < 4; j++) {
                size_t idx = base + col0 + j;
                Cout[idx] = res[idx] + acc[i][j] + bv[j];
            }
        } else {
            size_t base = (size_t)row * N + col0;
            #pragma unroll
            for (int j = 0; j < 4; j++) {
                float v = acc[i][j] + bv[j];
                if (MODE == 2) v = 0.5f * v * (1.f + erff(v * 0.70710678118654752f));
                if (MODE == 3) v += res[base + j];
                Cout[base + j] = v;
            }
        }
    }
}

// ---------------- launch ----------------
extern "C" void kernel_launch(void* const* d_in, const int* in_sizes, int n_in,
                              void* d_out, int out_size) {
    const float* x       = (const float*)d_in[0];
    const float* g1      = (const float*)d_in[1];
    const float* b1      = (const float*)d_in[2];
    const float* w_qkv   = (const float*)d_in[3];
    const float* b_qkv   = (const float*)d_in[4];
    const float* rel_pos = (const float*)d_in[5];
    const float* w_proj  = (const float*)d_in[6];
    const float* b_proj  = (const float*)d_in[7];
    const float* g2      = (const float*)d_in[8];
    const float* b2      = (const float*)d_in[9];
    const float* w_mlp1  = (const float*)d_in[10];
    const float* b_mlp1  = (const float*)d_in[11];
    const float* w_mlp2  = (const float*)d_in[12];
    const float* b_mlp2  = (const float*)d_in[13];
    float* out = (float*)d_out;

    float *p_hwin, *p_qkv, *p_attn, *p_x1, *p_h2, *p_hid;
    cudaGetSymbolAddress((void**)&p_hwin, g_hwin);
    cudaGetSymbolAddress((void**)&p_qkv,  g_qkv);
    cudaGetSymbolAddress((void**)&p_attn, g_attn);
    cudaGetSymbolAddress((void**)&p_x1,   g_x1);
    cudaGetSymbolAddress((void**)&p_h2,   g_h2);
    cudaGetSymbolAddress((void**)&p_hid,  g_hid);

    // 1. LN1 + roll + window partition
    ln1_window_kernel<<<TOK / 8, 256>>>(x, g1, b1);

    // 2. qkv GEMM: [65536,192] @ [192,576]
    gemm64_kernel<0><<<dim3(TOK / 64, 576 / 64), 256>>>(p_hwin, w_qkv, b_qkv, p_qkv, 576, 192, nullptr);

    // 3. windowed attention
    attn_kernel<<<BB * NW * NH, 256>>>(rel_pos);

    // 4. proj GEMM + un-window + un-roll + residual -> g_x1
    gemm64_kernel<1><<<dim3(TOK / 64, 192 / 64), 256>>>(p_attn, w_proj, b_proj, p_x1, 192, 192, x);

    // 5. LN2
    ln2_kernel<<<TOK / 8, 256>>>(g2, b2);

    // 6. mlp1 + gelu: [65536,192] @ [192,768]
    gemm64_kernel<2><<<dim3(TOK / 64, 768 / 64), 256>>>(p_h2, w_mlp1, b_mlp1, p_hid, 768, 192, nullptr);

    // 7. mlp2 + residual: [65536,768] @ [768,192] -> d_out
    gemm64_kernel<3><<<dim3(TOK / 64, 192 / 64), 256>>>(p_hid, w_mlp2, b_mlp2, out, 192, 768, p_x1);
}

// round 3
// speedup vs baseline: 2.2642x; 2.2642x over previous
#include <cuda_runtime.h>
#include <cuda_bf16.h>
#include <math.h>
#include <stdint.h>

// ---------------- problem constants ----------------
#define BB 16
#define HH 64
#define WW 64
#define CC 192
#define HD 32
#define NH 6
#define SH 4
#define NW 64
#define TOK (BB*HH*WW)        // 65536
#define PPW 64

// ---------------- scratch (device globals) ----------------
__device__ __nv_bfloat16 g_hwin_bf[TOK * CC];
__device__ __nv_bfloat16 g_qkv_bf [TOK * 3 * CC];
__device__ __nv_bfloat16 g_attn_bf[TOK * CC];
__device__ float         g_x1     [TOK * CC];
__device__ __nv_bfloat16 g_h2_bf  [TOK * CC];
__device__ __nv_bfloat16 g_hid_bf [TOK * 4 * CC];
__device__ __nv_bfloat16 g_wqkvT [576 * 192];
__device__ __nv_bfloat16 g_wprojT[192 * 192];
__device__ __nv_bfloat16 g_wmlp1T[768 * 192];
__device__ __nv_bfloat16 g_wmlp2T[192 * 768];

// ---------------- PTX helpers (family-portable: ldmatrix + mma.sync) ----------------
__device__ __forceinline__ uint32_t smem_u32(const void* p) {
    uint32_t a;
    asm("{ .reg .u64 t; cvta.to.shared.u64 t, %1; cvt.u32.u64 %0, t; }" : "=r"(a) : "l"(p));
    return a;
}
__device__ __forceinline__ void ldsm_x4(uint32_t* r, uint32_t addr) {
    asm volatile("ldmatrix.sync.aligned.m8n8.x4.shared.b16 {%0,%1,%2,%3}, [%4];"
        : "=r"(r[0]), "=r"(r[1]), "=r"(r[2]), "=r"(r[3]) : "r"(addr));
}
__device__ __forceinline__ void ldsm_x2(uint32_t* r, uint32_t addr) {
    asm volatile("ldmatrix.sync.aligned.m8n8.x2.shared.b16 {%0,%1}, [%2];"
        : "=r"(r[0]), "=r"(r[1]) : "r"(addr));
}
__device__ __forceinline__ void mma16816(float* c, const uint32_t* a, const uint32_t* b) {
    asm volatile(
        "mma.sync.aligned.m16n8k16.row.col.f32.bf16.bf16.f32 "
        "{%0,%1,%2,%3}, {%4,%5,%6,%7}, {%8,%9}, {%0,%1,%2,%3};"
        : "+f"(c[0]), "+f"(c[1]), "+f"(c[2]), "+f"(c[3])
        : "r"(a[0]), "r"(a[1]), "r"(a[2]), "r"(a[3]), "r"(b[0]), "r"(b[1]));
}

// ---------------- weight transpose + bf16 convert: wt[n*K+k] = w[k*N+n] ----------------
__global__ void wconv_kernel(const float* __restrict__ w, __nv_bfloat16* __restrict__ wt,
                             int K, int N) {
    int i = blockIdx.x * 256 + threadIdx.x;
    if (i < K * N) {
        int n = i / K, k = i - n * K;
        wt[i] = __float2bfloat16(w[k * N + n]);
    }
}

// ---------------- LN1 + roll(-4,-4) + window partition -> bf16 ----------------
__global__ void ln1_window_kernel(const float* __restrict__ x,
                                  const float* __restrict__ g,
                                  const float* __restrict__ b) {
    int warp = threadIdx.x >> 5;
    int lane = threadIdx.x & 31;
    int token = blockIdx.x * 8 + warp;
    int b_  = token >> 12;
    int rem = token & 4095;
    int wn  = rem >> 6;
    int t   = rem & 63;
    int y  = (((wn >> 3) << 3) + (t >> 3) + SH) & (HH - 1);
    int xx = (((wn & 7)  << 3) + (t & 7)  + SH) & (WW - 1);
    const float* src = x + (((size_t)b_ * HH + y) * WW + xx) * CC;

    float v[6];
    float s = 0.f;
    #pragma unroll
    for (int i = 0; i < 6; i++) { v[i] = src[lane + 32 * i]; s += v[i]; }
    #pragma unroll
    for (int o = 16; o; o >>= 1) s += __shfl_xor_sync(0xffffffffu, s, o);
    float mu = s * (1.f / CC);
    float s2 = 0.f;
    #pragma unroll
    for (int i = 0; i < 6; i++) { float d = v[i] - mu; s2 += d * d; }
    #pragma unroll
    for (int o = 16; o; o >>= 1) s2 += __shfl_xor_sync(0xffffffffu, s2, o);
    float inv = rsqrtf(s2 * (1.f / CC) + 1e-5f);

    __nv_bfloat16* dst = g_hwin_bf + (size_t)token * CC;
    #pragma unroll
    for (int i = 0; i < 6; i++) {
        int c = lane + 32 * i;
        dst[c] = __float2bfloat16((v[i] - mu) * inv * g[c] + b[c]);
    }
}

// ---------------- LN2 -> bf16 ----------------
__global__ void ln2_kernel(const float* __restrict__ g,
                           const float* __restrict__ b) {
    int warp = threadIdx.x >> 5;
    int lane = threadIdx.x & 31;
    int token = blockIdx.x * 8 + warp;
    const float* src = g_x1 + (size_t)token * CC;
    float v[6];
    float s = 0.f;
    #pragma unroll
    for (int i = 0; i < 6; i++) { v[i] = src[lane + 32 * i]; s += v[i]; }
    #pragma unroll
    for (int o = 16; o; o >>= 1) s += __shfl_xor_sync(0xffffffffu, s, o);
    float mu = s * (1.f / CC);
    float s2 = 0.f;
    #pragma unroll
    for (int i = 0; i < 6; i++) { float d = v[i] - mu; s2 += d * d; }
    #pragma unroll
    for (int o = 16; o; o >>= 1) s2 += __shfl_xor_sync(0xffffffffu, s2, o);
    float inv = rsqrtf(s2 * (1.f / CC) + 1e-5f);
    __nv_bfloat16* dst = g_h2_bf + (size_t)token * CC;
    #pragma unroll
    for (int i = 0; i < 6; i++) {
        int c = lane + 32 * i;
        dst[c] = __float2bfloat16((v[i] - mu) * inv * g[c] + b[c]);
    }
}

// ---------------- attention (bf16 in/out, fp32 compute) ----------------
__global__ __launch_bounds__(256)
void attn_kernel(const float* __restrict__ rel_pos) {
    __shared__ float qs[64][36];
    __shared__ float ks[64][36];
    __shared__ float vs[64][36];
    __shared__ float sc[64][65];

    int bid  = blockIdx.x;
    int head = bid % NH;
    int wnb  = bid / NH;
    int wn   = wnb % NW;
    int b_   = wnb / NW;
    int tokbase = (b_ * NW + wn) * PPW;
    bool lastRow = (wn >> 3) == 7;
    bool lastCol = (wn & 7) == 7;

    int tid = threadIdx.x;
    const __nv_bfloat16* qbase = g_qkv_bf + (size_t)tokbase * 576 + head * HD;
    #pragma unroll
    for (int i = 0; i < 8; i++) {
        int e = tid + 256 * i;
        int p = e >> 5, d = e & 31;
        const __nv_bfloat16* tp = qbase + (size_t)p * 576 + d;
        qs[p][d] = __bfloat162float(tp[0]);
        ks[p][d] = __bfloat162float(tp[192]);
        vs[p][d] = __bfloat162float(tp[384]);
    }
    __syncthreads();

    {
        int p  = tid >> 2;
        int jb = (tid & 3) * 16;
        float4 q0 = *(const float4*)&qs[p][0];
        float4 q1 = *(const float4*)&qs[p][4];
        float4 q2 = *(const float4*)&qs[p][8];
        float4 q3 = *(const float4*)&qs[p][12];
        float4 q4 = *(const float4*)&qs[p][16];
        float4 q5 = *(const float4*)&qs[p][20];
        float4 q6 = *(const float4*)&qs[p][24];
        float4 q7 = *(const float4*)&qs[p][28];
        int pi = p >> 3, pj = p & 7;
        const float* rp = rel_pos + head * 225;
        #pragma unroll
        for (int j = 0; j < 16; j++) {
            int qq = jb + j;
            const float* kr = &ks[qq][0];
            float4 k0 = *(const float4*)(kr + 0);
            float4 k1 = *(const float4*)(kr + 4);
            float4 k2 = *(const float4*)(kr + 8);
            float4 k3 = *(const float4*)(kr + 12);
            float4 k4 = *(const float4*)(kr + 16);
            float4 k5 = *(const float4*)(kr + 20);
            float4 k6 = *(const float4*)(kr + 24);
            float4 k7 = *(const float4*)(kr + 28);
            float s = q0.x*k0.x + q0.y*k0.y + q0.z*k0.z + q0.w*k0.w
                    + q1.x*k1.x + q1.y*k1.y + q1.z*k1.z + q1.w*k1.w
                    + q2.x*k2.x + q2.y*k2.y + q2.z*k2.z + q2.w*k2.w
                    + q3.x*k3.x + q3.y*k3.y + q3.z*k3.z + q3.w*k3.w
                    + q4.x*k4.x + q4.y*k4.y + q4.z*k4.z + q4.w*k4.w
                    + q5.x*k5.x + q5.y*k5.y + q5.z*k5.z + q5.w*k5.w
                    + q6.x*k6.x + q6.y*k6.y + q6.z*k6.z + q6.w*k6.w
                    + q7.x*k7.x + q7.y*k7.y + q7.z*k7.z + q7.w*k7.w;
            int qi = qq >> 3, qj = qq & 7;
            float bias = rp[(pi - qi + 7) * 15 + (pj - qj + 7)];
            s = s * 0.17677669529663687f + bias;
            bool m = (lastRow && ((pi < SH) != (qi < SH))) ||
                     (lastCol && ((pj < SH) != (qj < SH)));
            sc[p][qq] = m ? -INFINITY : s;
        }
    }
    __syncthreads();

    {
        int warp = tid >> 5, lane = tid & 31;
        #pragma unroll
        for (int rr = 0; rr < 8; rr++) {
            int r = warp * 8 + rr;
            float a = sc[r][lane];
            float c = sc[r][lane + 32];
            float mx = fmaxf(a, c);
            #pragma unroll
            for (int o = 16; o; o >>= 1) mx = fmaxf(mx, __shfl_xor_sync(0xffffffffu, mx, o));
            float e1 = __expf(a - mx);
            float e2 = __expf(c - mx);
            float sm = e1 + e2;
            #pragma unroll
            for (int o = 16; o; o >>= 1) sm += __shfl_xor_sync(0xffffffffu, sm, o);
            float invs = 1.f / sm;
            sc[r][lane]      = e1 * invs;
            sc[r][lane + 32] = e2 * invs;
        }
    }
    __syncthreads();

    {
        int p  = tid >> 2;
        int db = (tid & 3) * 8;
        float4 a0 = make_float4(0,0,0,0), a1 = make_float4(0,0,0,0);
        #pragma unroll 4
        for (int q = 0; q < 64; q++) {
            float pr = sc[p][q];
            float4 v0 = *(const float4*)&vs[q][db];
            float4 v1 = *(const float4*)&vs[q][db + 4];
            a0.x += pr * v0.x; a0.y += pr * v0.y; a0.z += pr * v0.z; a0.w += pr * v0.w;
            a1.x += pr * v1.x; a1.y += pr * v1.y; a1.z += pr * v1.z; a1.w += pr * v1.w;
        }
        __nv_bfloat16* dst = g_attn_bf + (size_t)(tokbase + p) * CC + head * HD + db;
        *(__nv_bfloat162*)(dst + 0) = __floats2bfloat162_rn(a0.x, a0.y);
        *(__nv_bfloat162*)(dst + 2) = __floats2bfloat162_rn(a0.z, a0.w);
        *(__nv_bfloat162*)(dst + 4) = __floats2bfloat162_rn(a1.x, a1.y);
        *(__nv_bfloat162*)(dst + 6) = __floats2bfloat162_rn(a1.z, a1.w);
    }
}

// ---------------- HMMA GEMM: block 128(M) x 64(N), BK=32, 4 warps ----------------
// A [M,K] bf16 row-major; BT [N,K] bf16 row-major (B col-major)
// warp tile 64x32: 4 m-tiles x 4 n-tiles of m16n8k16.
// MODE 0: qkv  -> bf16 out, stride 576, + bias
// MODE 1: proj -> remap window->pixel, fp32 out = res[pix] + acc + bias, stride 192
// MODE 2: mlp1 -> gelu(acc + bias), bf16 out, stride 768
// MODE 3: mlp2 -> fp32 out = res + acc + bias, stride 192
template <int MODE>
__global__ __launch_bounds__(128)
void gemm_mma(const __nv_bfloat16* __restrict__ A,
              const __nv_bfloat16* __restrict__ BT,
              const float* __restrict__ bias,
              void* __restrict__ outv,
              const float* __restrict__ res,
              int K) {
    __shared__ __align__(16) __nv_bfloat16 As[2][128][40];
    __shared__ __align__(16) __nv_bfloat16 Bs[2][64][40];

    int tid  = threadIdx.x;
    int lane = tid & 31;
    int wid  = tid >> 5;
    int wm   = wid & 1;        // 2 warps along M
    int wnw  = wid >> 1;       // 2 warps along N
    int m0 = blockIdx.x * 128;
    int n0 = blockIdx.y * 64;

    float acc[4][4][4];
    #pragma unroll
    for (int i = 0; i < 4; i++)
        #pragma unroll
        for (int j = 0; j < 4; j++)
            #pragma unroll
            for (int k = 0; k < 4; k++) acc[i][j][k] = 0.f;

    int ar = tid >> 2, acs = (tid & 3) * 8;          // A: rows 0..127 (4 passes)
    const int nch = K >> 5;

    // preload chunk 0 into buffer 0
    {
        #pragma unroll
        for (int i = 0; i < 4; i++) {
            int e = tid + 128 * i; int r = e >> 2, cs = (e & 3) * 8;
            *(uint4*)&As[0][r][cs] = *(const uint4*)(A + (size_t)(m0 + r) * K + cs);
        }
        #pragma unroll
        for (int i = 0; i < 2; i++) {
            int e = tid + 128 * i; int r = e >> 2, cs = (e & 3) * 8;
            *(uint4*)&Bs[0][r][cs] = *(const uint4*)(BT + (size_t)(n0 + r) * K + cs);
        }
    }
    __syncthreads();

    for (int c = 0; c < nch; c++) {
        int buf = c & 1;
        uint4 pa[4]; uint4 pb[2];
        if (c + 1 < nch) {
            int kc = (c + 1) * 32;
            #pragma unroll
            for (int i = 0; i < 4; i++) {
                int e = tid + 128 * i; int r = e >> 2, cs = (e & 3) * 8;
                pa[i] = *(const uint4*)(A + (size_t)(m0 + r) * K + kc + cs);
            }
            #pragma unroll
            for (int i = 0; i < 2; i++) {
                int e = tid + 128 * i; int r = e >> 2, cs = (e & 3) * 8;
                pb[i] = *(const uint4*)(BT + (size_t)(n0 + r) * K + kc + cs);
            }
        }

        uint32_t sA = smem_u32(&As[buf][0][0]);
        uint32_t sB = smem_u32(&Bs[buf][0][0]);
        #pragma unroll
        for (int ks = 0; ks < 2; ks++) {
            uint32_t a[4][4], b[4][2];
            #pragma unroll
            for (int mt = 0; mt < 4; mt++) {
                uint32_t addr = sA + ((wm * 64 + mt * 16 + (lane & 15)) * 40
                                      + ks * 16 + (lane >> 4) * 8) * 2;
                ldsm_x4(a[mt], addr);
            }
            #pragma unroll
            for (int nt = 0; nt < 4; nt++) {
                uint32_t addr = sB + ((wnw * 32 + nt * 8 + (lane & 7)) * 40
                                      + ks * 16 + ((lane >> 3) & 1) * 8) * 2;
                ldsm_x2(b[nt], addr);
            }
            #pragma unroll
            for (int mt = 0; mt < 4; mt++)
                #pragma unroll
                for (int nt = 0; nt < 4; nt++)
                    mma16816(acc[mt][nt], a[mt], b[nt]);
        }

        if (c + 1 < nch) {
            int nb = buf ^ 1;
            #pragma unroll
            for (int i = 0; i < 4; i++) {
                int e = tid + 128 * i; int r = e >> 2, cs = (e & 3) * 8;
                *(uint4*)&As[nb][r][cs] = pa[i];
            }
            #pragma unroll
            for (int i = 0; i < 2; i++) {
                int e = tid + 128 * i; int r = e >> 2, cs = (e & 3) * 8;
                *(uint4*)&Bs[nb][r][cs] = pb[i];
            }
            __syncthreads();
        }
    }

    // ---------------- epilogue ----------------
    #pragma unroll
    for (int mt = 0; mt < 4; mt++) {
        int rbase = m0 + wm * 64 + mt * 16 + (lane >> 2);
        #pragma unroll
        for (int half = 0; half < 2; half++) {
            int m = rbase + half * 8;
            size_t pixbase = 0;
            if (MODE == 1) {
                int b_ = m >> 12, rem = m & 4095, wnn = rem >> 6, t = rem & 63;
                int y  = (((wnn >> 3) << 3) + (t >> 3) + SH) & 63;
                int xx = (((wnn & 7)  << 3) + (t & 7)  + SH) & 63;
                pixbase = (size_t)(((b_ << 6) + y) * 64 + xx) * CC;
            }
            #pragma unroll
            for (int nt = 0; nt < 4; nt++) {
                int col = n0 + wnw * 32 + nt * 8 + (lane & 3) * 2;
                float v0 = acc[mt][nt][half * 2 + 0] + bias[col];
                float v1 = acc[mt][nt][half * 2 + 1] + bias[col + 1];
                if (MODE == 0) {
                    __nv_bfloat16* o = (__nv_bfloat16*)outv + (size_t)m * 576 + col;
                    *(__nv_bfloat162*)o = __floats2bfloat162_rn(v0, v1);
                } else if (MODE == 1) {
                    float* o = (float*)outv;
                    size_t i0 = pixbase + col;
                    o[i0]     = res[i0]     + v0;
                    o[i0 + 1] = res[i0 + 1] + v1;
                } else if (MODE == 2) {
                    v0 = 0.5f * v0 * (1.f + erff(v0 * 0.70710678118654752f));
                    v1 = 0.5f * v1 * (1.f + erff(v1 * 0.70710678118654752f));
                    __nv_bfloat16* o = (__nv_bfloat16*)outv + (size_t)m * 768 + col;
                    *(__nv_bfloat162*)o = __floats2bfloat162_rn(v0, v1);
                } else {
                    float* o = (float*)outv;
                    size_t i0 = (size_t)m * 192 + col;
                    o[i0]     = res[i0]     + v0;
                    o[i0 + 1] = res[i0 + 1] + v1;
                }
            }
        }
    }
}

// ---------------- launch ----------------
extern "C" void kernel_launch(void* const* d_in, const int* in_sizes, int n_in,
                              void* d_out, int out_size) {
    const float* x       = (const float*)d_in[0];
    const float* g1      = (const float*)d_in[1];
    const float* b1      = (const float*)d_in[2];
    const float* w_qkv   = (const float*)d_in[3];
    const float* b_qkv   = (const float*)d_in[4];
    const float* rel_pos = (const float*)d_in[5];
    const float* w_proj  = (const float*)d_in[6];
    const float* b_proj  = (const float*)d_in[7];
    const float* g2      = (const float*)d_in[8];
    const float* b2      = (const float*)d_in[9];
    const float* w_mlp1  = (const float*)d_in[10];
    const float* b_mlp1  = (const float*)d_in[11];
    const float* w_mlp2  = (const float*)d_in[12];
    const float* b_mlp2  = (const float*)d_in[13];
    float* out = (float*)d_out;

    __nv_bfloat16 *p_hwin, *p_qkv, *p_attn, *p_h2, *p_hid;
    __nv_bfloat16 *p_wqkvT, *p_wprojT, *p_wmlp1T, *p_wmlp2T;
    float *p_x1;
    cudaGetSymbolAddress((void**)&p_hwin,   g_hwin_bf);
    cudaGetSymbolAddress((void**)&p_qkv,    g_qkv_bf);
    cudaGetSymbolAddress((void**)&p_attn,   g_attn_bf);
    cudaGetSymbolAddress((void**)&p_x1,     g_x1);
    cudaGetSymbolAddress((void**)&p_h2,     g_h2_bf);
    cudaGetSymbolAddress((void**)&p_hid,    g_hid_bf);
    cudaGetSymbolAddress((void**)&p_wqkvT,  g_wqkvT);
    cudaGetSymbolAddress((void**)&p_wprojT, g_wprojT);
    cudaGetSymbolAddress((void**)&p_wmlp1T, g_wmlp1T);
    cudaGetSymbolAddress((void**)&p_wmlp2T, g_wmlp2T);

    // weight transpose + convert
    wconv_kernel<<<(192 * 576 + 255) / 256, 256>>>(w_qkv,  p_wqkvT,  192, 576);
    wconv_kernel<<<(192 * 192 + 255) / 256, 256>>>(w_proj, p_wprojT, 192, 192);
    wconv_kernel<<<(192 * 768 + 255) / 256, 256>>>(w_mlp1, p_wmlp1T, 192, 768);
    wconv_kernel<<<(768 * 192 + 255) / 256, 256>>>(w_mlp2, p_wmlp2T, 768, 192);

    // 1. LN1 + roll + window partition (bf16)
    ln1_window_kernel<<<TOK / 8, 256>>>(x, g1, b1);

    // 2. qkv: [65536,192] @ [192,576] -> bf16
    gemm_mma<0><<<dim3(TOK / 128, 9), 128>>>(p_hwin, p_wqkvT, b_qkv, p_qkv, nullptr, 192);

    // 3. windowed attention (bf16 io)
    attn_kernel<<<BB * NW * NH, 256>>>(rel_pos);

    // 4. proj + un-window + residual -> fp32 g_x1
    gemm_mma<1><<<dim3(TOK / 128, 3), 128>>>(p_attn, p_wprojT, b_proj, p_x1, x, 192);

    // 5. LN2 (bf16)
    ln2_kernel<<<TOK / 8, 256>>>(g2, b2);

    // 6. mlp1 + gelu: [65536,192] @ [192,768] -> bf16
    gemm_mma<2><<<dim3(TOK / 128, 12), 128>>>(p_h2, p_wmlp1T, b_mlp1, p_hid, nullptr, 192);

    // 7. mlp2 + residual: [65536,768] @ [768,192] -> fp32 out
    gemm_mma<3><<<dim3(TOK / 128, 3), 128>>>(p_hid, p_wmlp2T, b_mlp2, out, p_x1, 768);
}

// round 4
// speedup vs baseline: 4.0898x; 1.8063x over previous
#include <cuda_runtime.h>
#include <cuda_bf16.h>
#include <math.h>
#include <stdint.h>

// ---------------- problem constants ----------------
#define BB 16
#define HH 64
#define WW 64
#define CC 192
#define HD 32
#define NH 6
#define SH 4
#define NW 64
#define TOK (BB*HH*WW)        // 65536
#define PPW 64

// ---------------- scratch (device globals) ----------------
__device__ __nv_bfloat16 g_hwin_bf[TOK * CC];
__device__ __nv_bfloat16 g_qkv_bf [TOK * 3 * CC];
__device__ __nv_bfloat16 g_attn_bf[TOK * CC];
__device__ float         g_x1     [TOK * CC];
__device__ __nv_bfloat16 g_h2_bf  [TOK * CC];
__device__ __nv_bfloat16 g_hid_bf [TOK * 4 * CC];
__device__ __nv_bfloat16 g_wqkvT [576 * 192];
__device__ __nv_bfloat16 g_wprojT[192 * 192];
__device__ __nv_bfloat16 g_wmlp1T[768 * 192];
__device__ __nv_bfloat16 g_wmlp2T[192 * 768];

// ---------------- PTX helpers ----------------
__device__ __forceinline__ uint32_t smem_u32(const void* p) {
    uint32_t a;
    asm("{ .reg .u64 t; cvta.to.shared.u64 t, %1; cvt.u32.u64 %0, t; }" : "=r"(a) : "l"(p));
    return a;
}
__device__ __forceinline__ void ldsm_x4(uint32_t* r, uint32_t addr) {
    asm volatile("ldmatrix.sync.aligned.m8n8.x4.shared.b16 {%0,%1,%2,%3}, [%4];"
        : "=r"(r[0]), "=r"(r[1]), "=r"(r[2]), "=r"(r[3]) : "r"(addr));
}
__device__ __forceinline__ void ldsm_x2(uint32_t* r, uint32_t addr) {
    asm volatile("ldmatrix.sync.aligned.m8n8.x2.shared.b16 {%0,%1}, [%2];"
        : "=r"(r[0]), "=r"(r[1]) : "r"(addr));
}
__device__ __forceinline__ void ldsm_x2t(uint32_t* r, uint32_t addr) {
    asm volatile("ldmatrix.sync.aligned.m8n8.x2.trans.shared.b16 {%0,%1}, [%2];"
        : "=r"(r[0]), "=r"(r[1]) : "r"(addr));
}
__device__ __forceinline__ void mma16816(float* c, const uint32_t* a, const uint32_t* b) {
    asm volatile(
        "mma.sync.aligned.m16n8k16.row.col.f32.bf16.bf16.f32 "
        "{%0,%1,%2,%3}, {%4,%5,%6,%7}, {%8,%9}, {%0,%1,%2,%3};"
        : "+f"(c[0]), "+f"(c[1]), "+f"(c[2]), "+f"(c[3])
        : "r"(a[0]), "r"(a[1]), "r"(a[2]), "r"(a[3]), "r"(b[0]), "r"(b[1]));
}
__device__ __forceinline__ uint32_t packbf(float a, float b) {
    __nv_bfloat162 t = __floats2bfloat162_rn(a, b);
    return *(uint32_t*)&t;
}

// ---------------- weight transpose + bf16 convert: wt[n*K+k] = w[k*N+n] ----------------
__global__ void wconv_kernel(const float* __restrict__ w, __nv_bfloat16* __restrict__ wt,
                             int K, int N) {
    int i = blockIdx.x * 256 + threadIdx.x;
    if (i < K * N) {
        int n = i / K, k = i - n * K;
        wt[i] = __float2bfloat16(w[k * N + n]);
    }
}

// ---------------- LN1 + roll(-4,-4) + window partition -> bf16 ----------------
__global__ void ln1_window_kernel(const float* __restrict__ x,
                                  const float* __restrict__ g,
                                  const float* __restrict__ b) {
    int warp = threadIdx.x >> 5;
    int lane = threadIdx.x & 31;
    int token = blockIdx.x * 8 + warp;
    int b_  = token >> 12;
    int rem = token & 4095;
    int wn  = rem >> 6;
    int t   = rem & 63;
    int y  = (((wn >> 3) << 3) + (t >> 3) + SH) & (HH - 1);
    int xx = (((wn & 7)  << 3) + (t & 7)  + SH) & (WW - 1);
    const float* src = x + (((size_t)b_ * HH + y) * WW + xx) * CC;

    float v[6];
    float s = 0.f;
    #pragma unroll
    for (int i = 0; i < 6; i++) { v[i] = src[lane + 32 * i]; s += v[i]; }
    #pragma unroll
    for (int o = 16; o; o >>= 1) s += __shfl_xor_sync(0xffffffffu, s, o);
    float mu = s * (1.f / CC);
    float s2 = 0.f;
    #pragma unroll
    for (int i = 0; i < 6; i++) { float d = v[i] - mu; s2 += d * d; }
    #pragma unroll
    for (int o = 16; o; o >>= 1) s2 += __shfl_xor_sync(0xffffffffu, s2, o);
    float inv = rsqrtf(s2 * (1.f / CC) + 1e-5f);

    __nv_bfloat16* dst = g_hwin_bf + (size_t)token * CC;
    #pragma unroll
    for (int i = 0; i < 6; i++) {
        int c = lane + 32 * i;
        dst[c] = __float2bfloat16((v[i] - mu) * inv * g[c] + b[c]);
    }
}

// ---------------- LN2 -> bf16 ----------------
__global__ void ln2_kernel(const float* __restrict__ g,
                           const float* __restrict__ b) {
    int warp = threadIdx.x >> 5;
    int lane = threadIdx.x & 31;
    int token = blockIdx.x * 8 + warp;
    const float* src = g_x1 + (size_t)token * CC;
    float v[6];
    float s = 0.f;
    #pragma unroll
    for (int i = 0; i < 6; i++) { v[i] = src[lane + 32 * i]; s += v[i]; }
    #pragma unroll
    for (int o = 16; o; o >>= 1) s += __shfl_xor_sync(0xffffffffu, s, o);
    float mu = s * (1.f / CC);
    float s2 = 0.f;
    #pragma unroll
    for (int i = 0; i < 6; i++) { float d = v[i] - mu; s2 += d * d; }
    #pragma unroll
    for (int o = 16; o; o >>= 1) s2 += __shfl_xor_sync(0xffffffffu, s2, o);
    float inv = rsqrtf(s2 * (1.f / CC) + 1e-5f);
    __nv_bfloat16* dst = g_h2_bf + (size_t)token * CC;
    #pragma unroll
    for (int i = 0; i < 6; i++) {
        int c = lane + 32 * i;
        dst[c] = __float2bfloat16((v[i] - mu) * inv * g[c] + b[c]);
    }
}

// ---------------- HMMA attention: 1 block = 1 window, 12 warps = 2 per head ----------------
// smem: qs/ks/vs [6 heads][64][40] bf16 + rel bias [6][225] fp32
#define AT_SMEM (30720*3 + 5400*4 + 64)
__global__ __launch_bounds__(384)
void attn_mma_kernel(const float* __restrict__ rel_pos) {
    extern __shared__ char sm[];
    __nv_bfloat16* qs = (__nv_bfloat16*)sm;
    __nv_bfloat16* ks = (__nv_bfloat16*)(sm + 30720);
    __nv_bfloat16* vs = (__nv_bfloat16*)(sm + 61440);
    float*         rs = (float*)(sm + 92160);

    int tid = threadIdx.x;
    int wn  = blockIdx.x & 63;
    int tokbase = blockIdx.x * 64;
    bool lastRow = (wn >> 3) == 7;
    bool lastCol = (wn & 7) == 7;

    // load qkv window tile: 64 tokens x 576 chans (72 uint4/row)
    {
        const uint4* src = (const uint4*)(g_qkv_bf + (size_t)tokbase * 576);
        #pragma unroll
        for (int i = 0; i < 12; i++) {
            int e = tid + 384 * i;            // 0..4607
            int r = e / 72, c8 = e % 72;
            uint4 v = src[r * 72 + c8];
            int sect = c8 / 24;               // 0=q 1=k 2=v
            int c8l = c8 % 24;
            int h = c8l >> 2;
            int off = (c8l & 3) * 8;
            __nv_bfloat16* buf = sect == 0 ? qs : (sect == 1 ? ks : vs);
            *(uint4*)&buf[h * 2560 + r * 40 + off] = v;
        }
        for (int i = tid; i < NH * 225; i += 384) rs[i] = rel_pos[i];
    }
    __syncthreads();

    int wid = tid >> 5, lane = tid & 31;
    int head = wid >> 1;
    int mhalf = wid & 1;                      // which 32 query rows
    uint32_t qb = smem_u32(qs + head * 2560);
    uint32_t kb = smem_u32(ks + head * 2560);
    uint32_t vb = smem_u32(vs + head * 2560);

    // ---- S = Q K^T : warp computes 32(q) x 64(k), fp32 accum ----
    float sacc[2][8][4];
    #pragma unroll
    for (int mt = 0; mt < 2; mt++)
        #pragma unroll
        for (int nt = 0; nt < 8; nt++)
            #pragma unroll
            for (int e = 0; e < 4; e++) sacc[mt][nt][e] = 0.f;

    int L = lane & 15;
    #pragma unroll
    for (int ks16 = 0; ks16 < 2; ks16++) {
        uint32_t a[2][4];
        #pragma unroll
        for (int mt = 0; mt < 2; mt++) {
            int row = mhalf * 32 + mt * 16 + (lane & 15);
            ldsm_x4(a[mt], qb + (row * 40 + ks16 * 16 + (lane >> 4) * 8) * 2);
        }
        uint32_t bf[8][2];
        #pragma unroll
        for (int nt = 0; nt < 8; nt++)
            ldsm_x2(bf[nt], kb + ((nt * 8 + (L & 7)) * 40 + ks16 * 16 + (L >> 3) * 8) * 2);
        #pragma unroll
        for (int mt = 0; mt < 2; mt++)
            #pragma unroll
            for (int nt = 0; nt < 8; nt++)
                mma16816(sacc[mt][nt], a[mt], bf[nt]);
    }

    // ---- bias + mask + softmax (rows live in 4-lane groups) ----
    const float* rph = rs + head * 225;
    #pragma unroll
    for (int mt = 0; mt < 2; mt++) {
        #pragma unroll
        for (int half = 0; half < 2; half++) {
            int p = mhalf * 32 + mt * 16 + (lane >> 2) + half * 8;
            int pi = p >> 3, pj = p & 7;
            float mx = -INFINITY;
            #pragma unroll
            for (int nt = 0; nt < 8; nt++) {
                #pragma unroll
                for (int e = 0; e < 2; e++) {
                    int qt = nt * 8 + (lane & 3) * 2 + e;
                    int qi = qt >> 3, qj = qt & 7;
                    float s = sacc[mt][nt][half * 2 + e] * 0.17677669529663687f
                            + rph[(pi - qi + 7) * 15 + (pj - qj + 7)];
                    bool msk = (lastRow && ((pi < SH) != (qi < SH))) ||
                               (lastCol && ((pj < SH) != (qj < SH)));
                    s = msk ? -INFINITY : s;
                    sacc[mt][nt][half * 2 + e] = s;
                    mx = fmaxf(mx, s);
                }
            }
            mx = fmaxf(mx, __shfl_xor_sync(0xffffffffu, mx, 1));
            mx = fmaxf(mx, __shfl_xor_sync(0xffffffffu, mx, 2));
            float sum = 0.f;
            #pragma unroll
            for (int nt = 0; nt < 8; nt++) {
                #pragma unroll
                for (int e = 0; e < 2; e++) {
                    float ex = __expf(sacc[mt][nt][half * 2 + e] - mx);
                    sacc[mt][nt][half * 2 + e] = ex;
                    sum += ex;
                }
            }
            sum += __shfl_xor_sync(0xffffffffu, sum, 1);
            sum += __shfl_xor_sync(0xffffffffu, sum, 2);
            float inv = 1.f / sum;
            #pragma unroll
            for (int nt = 0; nt < 8; nt++) {
                #pragma unroll
                for (int e = 0; e < 2; e++)
                    sacc[mt][nt][half * 2 + e] *= inv;
            }
        }
    }

    // ---- O = P V : P from regs (A frag), V via ldmatrix.trans (B frag) ----
    float o[2][4][4];
    #pragma unroll
    for (int mt = 0; mt < 2; mt++)
        #pragma unroll
        for (int nt = 0; nt < 4; nt++)
            #pragma unroll
            for (int e = 0; e < 4; e++) o[mt][nt][e] = 0.f;

    #pragma unroll
    for (int j = 0; j < 4; j++) {            // 16 key tokens per step
        uint32_t bf[4][2];
        #pragma unroll
        for (int nt = 0; nt < 4; nt++)
            ldsm_x2t(bf[nt], vb + ((j * 16 + (L & 7) + (L >> 3) * 8) * 40 + nt * 8) * 2);
        #pragma unroll
        for (int mt = 0; mt < 2; mt++) {
            uint32_t afr[4];
            afr[0] = packbf(sacc[mt][2 * j    ][0], sacc[mt][2 * j    ][1]);
            afr[1] = packbf(sacc[mt][2 * j    ][2], sacc[mt][2 * j    ][3]);
            afr[2] = packbf(sacc[mt][2 * j + 1][0], sacc[mt][2 * j + 1][1]);
            afr[3] = packbf(sacc[mt][2 * j + 1][2], sacc[mt][2 * j + 1][3]);
            #pragma unroll
            for (int nt = 0; nt < 4; nt++)
                mma16816(o[mt][nt], afr, bf[nt]);
        }
    }

    // ---- store: g_attn_bf[(tokbase+p)*192 + head*32 + d] ----
    #pragma unroll
    for (int mt = 0; mt < 2; mt++) {
        int prow = mhalf * 32 + mt * 16 + (lane >> 2);
        #pragma unroll
        for (int nt = 0; nt < 4; nt++) {
            int col = head * 32 + nt * 8 + (lane & 3) * 2;
            __nv_bfloat16* dst = g_attn_bf + (size_t)(tokbase + prow) * CC + col;
            *(__nv_bfloat162*)dst = __floats2bfloat162_rn(o[mt][nt][0], o[mt][nt][1]);
            __nv_bfloat16* dst2 = dst + 8 * CC;
            *(__nv_bfloat162*)dst2 = __floats2bfloat162_rn(o[mt][nt][2], o[mt][nt][3]);
        }
    }
}

// ---------------- HMMA GEMM: block 256(M) x 64(N), BK=32, 8 warps ----------------
// warp grid 4(M) x 2(N); warp tile 64x32 (4 m-tiles x 4 n-tiles of m16n8k16)
// MODE 0: qkv -> bf16, stride 576, +bias
// MODE 1: proj -> window->pixel remap, fp32 out = res[pix]+acc+bias
// MODE 2: mlp1 -> gelu(acc+bias), bf16, stride 768
// MODE 3: mlp2 -> fp32 out = res+acc+bias, stride 192
#define GEMM_SMEM (2*256*40*2 + 2*64*40*2)
template <int MODE>
__global__ __launch_bounds__(256)
void gemm_mma(const __nv_bfloat16* __restrict__ A,
              const __nv_bfloat16* __restrict__ BT,
              const float* __restrict__ bias,
              void* __restrict__ outv,
              const float* __restrict__ res,
              int K) {
    extern __shared__ char gsm[];
    __nv_bfloat16* As = (__nv_bfloat16*)gsm;             // [2][256][40]
    __nv_bfloat16* Bs = (__nv_bfloat16*)(gsm + 40960);   // [2][64][40]

    int tid  = threadIdx.x;
    int lane = tid & 31;
    int wid  = tid >> 5;
    int wm   = wid & 3;
    int wnw  = wid >> 2;
    int m0 = blockIdx.x * 256;
    int n0 = blockIdx.y * 64;

    float acc[4][4][4];
    #pragma unroll
    for (int i = 0; i < 4; i++)
        #pragma unroll
        for (int j = 0; j < 4; j++)
            #pragma unroll
            for (int k = 0; k < 4; k++) acc[i][j][k] = 0.f;

    const int nch = K >> 5;

    // preload chunk 0
    {
        #pragma unroll
        for (int i = 0; i < 4; i++) {
            int e = tid + 256 * i; int r = e >> 2, cs = (e & 3) * 8;
            *(uint4*)&As[r * 40 + cs] = *(const uint4*)(A + (size_t)(m0 + r) * K + cs);
        }
        int r = tid >> 2, cs = (tid & 3) * 8;
        *(uint4*)&Bs[r * 40 + cs] = *(const uint4*)(BT + (size_t)(n0 + r) * K + cs);
    }
    __syncthreads();

    for (int c = 0; c < nch; c++) {
        int buf = c & 1;
        uint4 pa[4]; uint4 pb;
        if (c + 1 < nch) {
            int kc = (c + 1) * 32;
            #pragma unroll
            for (int i = 0; i < 4; i++) {
                int e = tid + 256 * i; int r = e >> 2, cs = (e & 3) * 8;
                pa[i] = *(const uint4*)(A + (size_t)(m0 + r) * K + kc + cs);
            }
            int r = tid >> 2, cs = (tid & 3) * 8;
            pb = *(const uint4*)(BT + (size_t)(n0 + r) * K + kc + cs);
        }

        uint32_t sA = smem_u32(As + buf * 10240);
        uint32_t sB = smem_u32(Bs + buf * 2560);
        #pragma unroll
        for (int ks = 0; ks < 2; ks++) {
            uint32_t a[4][4], b[4][2];
            #pragma unroll
            for (int mt = 0; mt < 4; mt++) {
                uint32_t addr = sA + ((wm * 64 + mt * 16 + (lane & 15)) * 40
                                      + ks * 16 + (lane >> 4) * 8) * 2;
                ldsm_x4(a[mt], addr);
            }
            #pragma unroll
            for (int nt = 0; nt < 4; nt++) {
                uint32_t addr = sB + ((wnw * 32 + nt * 8 + (lane & 7)) * 40
                                      + ks * 16 + ((lane >> 3) & 1) * 8) * 2;
                ldsm_x2(b[nt], addr);
            }
            #pragma unroll
            for (int mt = 0; mt < 4; mt++)
                #pragma unroll
                for (int nt = 0; nt < 4; nt++)
                    mma16816(acc[mt][nt], a[mt], b[nt]);
        }

        if (c + 1 < nch) {
            int nb = buf ^ 1;
            #pragma unroll
            for (int i = 0; i < 4; i++) {
                int e = tid + 256 * i; int r = e >> 2, cs = (e & 3) * 8;
                *(uint4*)&As[nb * 10240 + r * 40 + cs] = pa[i];
            }
            int r = tid >> 2, cs = (tid & 3) * 8;
            *(uint4*)&Bs[nb * 2560 + r * 40 + cs] = pb;
            __syncthreads();
        }
    }

    // ---------------- epilogue ----------------
    #pragma unroll
    for (int mt = 0; mt < 4; mt++) {
        int rbase = m0 + wm * 64 + mt * 16 + (lane >> 2);
        #pragma unroll
        for (int half = 0; half < 2; half++) {
            int m = rbase + half * 8;
            size_t pixbase = 0;
            if (MODE == 1) {
                int b_ = m >> 12, rem = m & 4095, wnn = rem >> 6, t = rem & 63;
                int y  = (((wnn >> 3) << 3) + (t >> 3) + SH) & 63;
                int xx = (((wnn & 7)  << 3) + (t & 7)  + SH) & 63;
                pixbase = (size_t)(((b_ << 6) + y) * 64 + xx) * CC;
            }
            #pragma unroll
            for (int nt = 0; nt < 4; nt++) {
                int col = n0 + wnw * 32 + nt * 8 + (lane & 3) * 2;
                float v0 = acc[mt][nt][half * 2 + 0] + bias[col];
                float v1 = acc[mt][nt][half * 2 + 1] + bias[col + 1];
                if (MODE == 0) {
                    __nv_bfloat16* o = (__nv_bfloat16*)outv + (size_t)m * 576 + col;
                    *(__nv_bfloat162*)o = __floats2bfloat162_rn(v0, v1);
                } else if (MODE == 1) {
                    float* o = (float*)outv;
                    size_t i0 = pixbase + col;
                    o[i0]     = res[i0]     + v0;
                    o[i0 + 1] = res[i0 + 1] + v1;
                } else if (MODE == 2) {
                    v0 = 0.5f * v0 * (1.f + erff(v0 * 0.70710678118654752f));
                    v1 = 0.5f * v1 * (1.f + erff(v1 * 0.70710678118654752f));
                    __nv_bfloat16* o = (__nv_bfloat16*)outv + (size_t)m * 768 + col;
                    *(__nv_bfloat162*)o = __floats2bfloat162_rn(v0, v1);
                } else {
                    float* o = (float*)outv;
                    size_t i0 = (size_t)m * 192 + col;
                    o[i0]     = res[i0]     + v0;
                    o[i0 + 1] = res[i0 + 1] + v1;
                }
            }
        }
    }
}

// ---------------- launch ----------------
extern "C" void kernel_launch(void* const* d_in, const int* in_sizes, int n_in,
                              void* d_out, int out_size) {
    const float* x       = (const float*)d_in[0];
    const float* g1      = (const float*)d_in[1];
    const float* b1      = (const float*)d_in[2];
    const float* w_qkv   = (const float*)d_in[3];
    const float* b_qkv   = (const float*)d_in[4];
    const float* rel_pos = (const float*)d_in[5];
    const float* w_proj  = (const float*)d_in[6];
    const float* b_proj  = (const float*)d_in[7];
    const float* g2      = (const float*)d_in[8];
    const float* b2      = (const float*)d_in[9];
    const float* w_mlp1  = (const float*)d_in[10];
    const float* b_mlp1  = (const float*)d_in[11];
    const float* w_mlp2  = (const float*)d_in[12];
    const float* b_mlp2  = (const float*)d_in[13];
    float* out = (float*)d_out;

    __nv_bfloat16 *p_hwin, *p_qkv, *p_attn, *p_h2, *p_hid;
    __nv_bfloat16 *p_wqkvT, *p_wprojT, *p_wmlp1T, *p_wmlp2T;
    float *p_x1;
    cudaGetSymbolAddress((void**)&p_hwin,   g_hwin_bf);
    cudaGetSymbolAddress((void**)&p_qkv,    g_qkv_bf);
    cudaGetSymbolAddress((void**)&p_attn,   g_attn_bf);
    cudaGetSymbolAddress((void**)&p_x1,     g_x1);
    cudaGetSymbolAddress((void**)&p_h2,     g_h2_bf);
    cudaGetSymbolAddress((void**)&p_hid,    g_hid_bf);
    cudaGetSymbolAddress((void**)&p_wqkvT,  g_wqkvT);
    cudaGetSymbolAddress((void**)&p_wprojT, g_wprojT);
    cudaGetSymbolAddress((void**)&p_wmlp1T, g_wmlp1T);
    cudaGetSymbolAddress((void**)&p_wmlp2T, g_wmlp2T);

    cudaFuncSetAttribute(gemm_mma<0>, cudaFuncAttributeMaxDynamicSharedMemorySize, GEMM_SMEM);
    cudaFuncSetAttribute(gemm_mma<1>, cudaFuncAttributeMaxDynamicSharedMemorySize, GEMM_SMEM);
    cudaFuncSetAttribute(gemm_mma<2>, cudaFuncAttributeMaxDynamicSharedMemorySize, GEMM_SMEM);
    cudaFuncSetAttribute(gemm_mma<3>, cudaFuncAttributeMaxDynamicSharedMemorySize, GEMM_SMEM);
    cudaFuncSetAttribute(attn_mma_kernel, cudaFuncAttributeMaxDynamicSharedMemorySize, AT_SMEM);

    // weight transpose + convert
    wconv_kernel<<<(192 * 576 + 255) / 256, 256>>>(w_qkv,  p_wqkvT,  192, 576);
    wconv_kernel<<<(192 * 192 + 255) / 256, 256>>>(w_proj, p_wprojT, 192, 192);
    wconv_kernel<<<(192 * 768 + 255) / 256, 256>>>(w_mlp1, p_wmlp1T, 192, 768);
    wconv_kernel<<<(768 * 192 + 255) / 256, 256>>>(w_mlp2, p_wmlp2T, 768, 192);

    // 1. LN1 + roll + window partition (bf16)
    ln1_window_kernel<<<TOK / 8, 256>>>(x, g1, b1);

    // 2. qkv: [65536,192] @ [192,576] -> bf16
    gemm_mma<0><<<dim3(TOK / 256, 9), 256, GEMM_SMEM>>>(p_hwin, p_wqkvT, b_qkv, p_qkv, nullptr, 192);

    // 3. windowed attention (HMMA)
    attn_mma_kernel<<<BB * NW, 384, AT_SMEM>>>(rel_pos);

    // 4. proj + un-window + residual -> fp32 g_x1
    gemm_mma<1><<<dim3(TOK / 256, 3), 256, GEMM_SMEM>>>(p_attn, p_wprojT, b_proj, p_x1, x, 192);

    // 5. LN2 (bf16)
    ln2_kernel<<<TOK / 8, 256>>>(g2, b2);

    // 6. mlp1 + gelu: [65536,192] @ [192,768] -> bf16
    gemm_mma<2><<<dim3(TOK / 256, 12), 256, GEMM_SMEM>>>(p_h2, p_wmlp1T, b_mlp1, p_hid, nullptr, 192);

    // 7. mlp2 + residual: [65536,768] @ [768,192] -> fp32 out
    gemm_mma<3><<<dim3(TOK / 256, 3), 256, GEMM_SMEM>>>(p_hid, p_wmlp2T, b_mlp2, out, p_x1, 768);
}

// round 5
// speedup vs baseline: 4.1101x; 1.0050x over previous
#include <cuda_runtime.h>
#include <cuda_bf16.h>
#include <math.h>
#include <stdint.h>

// ---------------- problem constants ----------------
#define BB 16
#define HH 64
#define WW 64
#define CC 192
#define HD 32
#define NH 6
#define SH 4
#define NW 64
#define TOK (BB*HH*WW)        // 65536
#define PPW 64

// ---------------- scratch (device globals) ----------------
__device__ __nv_bfloat16 g_hwin_bf[TOK * CC];
__device__ __nv_bfloat16 g_qkv_bf [TOK * 3 * CC];
__device__ __nv_bfloat16 g_attn_bf[TOK * CC];
__device__ float         g_x1     [TOK * CC];
__device__ __nv_bfloat16 g_h2_bf  [TOK * CC];
__device__ __nv_bfloat16 g_hid_bf [TOK * 4 * CC];
__device__ __nv_bfloat16 g_wqkvT [576 * 192];
__device__ __nv_bfloat16 g_wprojT[192 * 192];
__device__ __nv_bfloat16 g_wmlp1T[768 * 192];
__device__ __nv_bfloat16 g_wmlp2T[192 * 768];

// ---------------- PTX helpers ----------------
__device__ __forceinline__ uint32_t smem_u32(const void* p) {
    uint32_t a;
    asm("{ .reg .u64 t; cvta.to.shared.u64 t, %1; cvt.u32.u64 %0, t; }" : "=r"(a) : "l"(p));
    return a;
}
__device__ __forceinline__ void ldsm_x4(uint32_t* r, uint32_t addr) {
    asm volatile("ldmatrix.sync.aligned.m8n8.x4.shared.b16 {%0,%1,%2,%3}, [%4];"
        : "=r"(r[0]), "=r"(r[1]), "=r"(r[2]), "=r"(r[3]) : "r"(addr));
}
__device__ __forceinline__ void ldsm_x2(uint32_t* r, uint32_t addr) {
    asm volatile("ldmatrix.sync.aligned.m8n8.x2.shared.b16 {%0,%1}, [%2];"
        : "=r"(r[0]), "=r"(r[1]) : "r"(addr));
}
__device__ __forceinline__ void ldsm_x2t(uint32_t* r, uint32_t addr) {
    asm volatile("ldmatrix.sync.aligned.m8n8.x2.trans.shared.b16 {%0,%1}, [%2];"
        : "=r"(r[0]), "=r"(r[1]) : "r"(addr));
}
__device__ __forceinline__ void mma16816(float* c, const uint32_t* a, const uint32_t* b) {
    asm volatile(
        "mma.sync.aligned.m16n8k16.row.col.f32.bf16.bf16.f32 "
        "{%0,%1,%2,%3}, {%4,%5,%6,%7}, {%8,%9}, {%0,%1,%2,%3};"
        : "+f"(c[0]), "+f"(c[1]), "+f"(c[2]), "+f"(c[3])
        : "r"(a[0]), "r"(a[1]), "r"(a[2]), "r"(a[3]), "r"(b[0]), "r"(b[1]));
}
__device__ __forceinline__ uint32_t packbf(float a, float b) {
    __nv_bfloat162 t = __floats2bfloat162_rn(a, b);
    return *(uint32_t*)&t;
}
#define CP16(dst, src) \
    asm volatile("cp.async.cg.shared.global [%0], [%1], 16;" :: "r"(dst), "l"(src))
#define CPCOMMIT() asm volatile("cp.async.commit_group;" ::)
#define CPWAIT1()  asm volatile("cp.async.wait_group 1;" ::)
#define CPWAIT0()  asm volatile("cp.async.wait_group 0;" ::)

// ---------------- all-weights transpose + bf16 convert in ONE launch ----------------
__global__ void wconv_all(const float* __restrict__ w0, __nv_bfloat16* __restrict__ t0,
                          const float* __restrict__ w1, __nv_bfloat16* __restrict__ t1,
                          const float* __restrict__ w2, __nv_bfloat16* __restrict__ t2,
                          const float* __restrict__ w3, __nv_bfloat16* __restrict__ t3) {
    int bid = blockIdx.x;
    const float* w; __nv_bfloat16* t; int K, N, base;
    if      (bid < 432)  { w = w0; t = t0; K = 192; N = 576; base = bid; }
    else if (bid < 576)  { w = w1; t = t1; K = 192; N = 192; base = bid - 432; }
    else if (bid < 1152) { w = w2; t = t2; K = 192; N = 768; base = bid - 576; }
    else                 { w = w3; t = t3; K = 768; N = 192; base = bid - 1152; }
    int i = base * 256 + threadIdx.x;
    if (i < K * N) {
        int n = i / K, k = i - n * K;
        t[i] = __float2bfloat16(w[k * N + n]);
    }
}

// ---------------- LN1 + roll(-4,-4) + window partition -> bf16 ----------------
__global__ void ln1_window_kernel(const float* __restrict__ x,
                                  const float* __restrict__ g,
                                  const float* __restrict__ b) {
    int warp = threadIdx.x >> 5;
    int lane = threadIdx.x & 31;
    int token = blockIdx.x * 8 + warp;
    int b_  = token >> 12;
    int rem = token & 4095;
    int wn  = rem >> 6;
    int t   = rem & 63;
    int y  = (((wn >> 3) << 3) + (t >> 3) + SH) & (HH - 1);
    int xx = (((wn & 7)  << 3) + (t & 7)  + SH) & (WW - 1);
    const float* src = x + (((size_t)b_ * HH + y) * WW + xx) * CC;

    float v[6];
    float s = 0.f;
    #pragma unroll
    for (int i = 0; i < 6; i++) { v[i] = src[lane + 32 * i]; s += v[i]; }
    #pragma unroll
    for (int o = 16; o; o >>= 1) s += __shfl_xor_sync(0xffffffffu, s, o);
    float mu = s * (1.f / CC);
    float s2 = 0.f;
    #pragma unroll
    for (int i = 0; i < 6; i++) { float d = v[i] - mu; s2 += d * d; }
    #pragma unroll
    for (int o = 16; o; o >>= 1) s2 += __shfl_xor_sync(0xffffffffu, s2, o);
    float inv = rsqrtf(s2 * (1.f / CC) + 1e-5f);

    __nv_bfloat16* dst = g_hwin_bf + (size_t)token * CC;
    #pragma unroll
    for (int i = 0; i < 6; i++) {
        int c = lane + 32 * i;
        dst[c] = __float2bfloat16((v[i] - mu) * inv * g[c] + b[c]);
    }
}

// ---------------- HMMA attention: 1 block = 1 window, 12 warps = 2 per head ----------------
#define AT_SMEM (30720*3 + 5400*4 + 64)
__global__ __launch_bounds__(384)
void attn_mma_kernel(const float* __restrict__ rel_pos) {
    extern __shared__ char sm[];
    __nv_bfloat16* qs = (__nv_bfloat16*)sm;
    __nv_bfloat16* ks = (__nv_bfloat16*)(sm + 30720);
    __nv_bfloat16* vs = (__nv_bfloat16*)(sm + 61440);
    float*         rs = (float*)(sm + 92160);

    int tid = threadIdx.x;
    int wn  = blockIdx.x & 63;
    int tokbase = blockIdx.x * 64;
    bool lastRow = (wn >> 3) == 7;
    bool lastCol = (wn & 7) == 7;

    {
        const uint4* src = (const uint4*)(g_qkv_bf + (size_t)tokbase * 576);
        #pragma unroll
        for (int i = 0; i < 12; i++) {
            int e = tid + 384 * i;
            int r = e / 72, c8 = e % 72;
            uint4 v = src[r * 72 + c8];
            int sect = c8 / 24;
            int c8l = c8 % 24;
            int h = c8l >> 2;
            int off = (c8l & 3) * 8;
            __nv_bfloat16* buf = sect == 0 ? qs : (sect == 1 ? ks : vs);
            *(uint4*)&buf[h * 2560 + r * 40 + off] = v;
        }
        for (int i = tid; i < NH * 225; i += 384) rs[i] = rel_pos[i];
    }
    __syncthreads();

    int wid = tid >> 5, lane = tid & 31;
    int head = wid >> 1;
    int mhalf = wid & 1;
    uint32_t qb = smem_u32(qs + head * 2560);
    uint32_t kb = smem_u32(ks + head * 2560);
    uint32_t vb = smem_u32(vs + head * 2560);

    float sacc[2][8][4];
    #pragma unroll
    for (int mt = 0; mt < 2; mt++)
        #pragma unroll
        for (int nt = 0; nt < 8; nt++)
            #pragma unroll
            for (int e = 0; e < 4; e++) sacc[mt][nt][e] = 0.f;

    int L = lane & 15;
    #pragma unroll
    for (int ks16 = 0; ks16 < 2; ks16++) {
        uint32_t a[2][4];
        #pragma unroll
        for (int mt = 0; mt < 2; mt++) {
            int row = mhalf * 32 + mt * 16 + (lane & 15);
            ldsm_x4(a[mt], qb + (row * 40 + ks16 * 16 + (lane >> 4) * 8) * 2);
        }
        uint32_t bf[8][2];
        #pragma unroll
        for (int nt = 0; nt < 8; nt++)
            ldsm_x2(bf[nt], kb + ((nt * 8 + (L & 7)) * 40 + ks16 * 16 + (L >> 3) * 8) * 2);
        #pragma unroll
        for (int mt = 0; mt < 2; mt++)
            #pragma unroll
            for (int nt = 0; nt < 8; nt++)
                mma16816(sacc[mt][nt], a[mt], bf[nt]);
    }

    const float* rph = rs + head * 225;
    #pragma unroll
    for (int mt = 0; mt < 2; mt++) {
        #pragma unroll
        for (int half = 0; half < 2; half++) {
            int p = mhalf * 32 + mt * 16 + (lane >> 2) + half * 8;
            int pi = p >> 3, pj = p & 7;
            float mx = -INFINITY;
            #pragma unroll
            for (int nt = 0; nt < 8; nt++) {
                #pragma unroll
                for (int e = 0; e < 2; e++) {
                    int qt = nt * 8 + (lane & 3) * 2 + e;
                    int qi = qt >> 3, qj = qt & 7;
                    float s = sacc[mt][nt][half * 2 + e] * 0.17677669529663687f
                            + rph[(pi - qi + 7) * 15 + (pj - qj + 7)];
                    bool msk = (lastRow && ((pi < SH) != (qi < SH))) ||
                               (lastCol && ((pj < SH) != (qj < SH)));
                    s = msk ? -INFINITY : s;
                    sacc[mt][nt][half * 2 + e] = s;
                    mx = fmaxf(mx, s);
                }
            }
            mx = fmaxf(mx, __shfl_xor_sync(0xffffffffu, mx, 1));
            mx = fmaxf(mx, __shfl_xor_sync(0xffffffffu, mx, 2));
            float sum = 0.f;
            #pragma unroll
            for (int nt = 0; nt < 8; nt++) {
                #pragma unroll
                for (int e = 0; e < 2; e++) {
                    float ex = __expf(sacc[mt][nt][half * 2 + e] - mx);
                    sacc[mt][nt][half * 2 + e] = ex;
                    sum += ex;
                }
            }
            sum += __shfl_xor_sync(0xffffffffu, sum, 1);
            sum += __shfl_xor_sync(0xffffffffu, sum, 2);
            float inv = 1.f / sum;
            #pragma unroll
            for (int nt = 0; nt < 8; nt++) {
                #pragma unroll
                for (int e = 0; e < 2; e++)
                    sacc[mt][nt][half * 2 + e] *= inv;
            }
        }
    }

    float o[2][4][4];
    #pragma unroll
    for (int mt = 0; mt < 2; mt++)
        #pragma unroll
        for (int nt = 0; nt < 4; nt++)
            #pragma unroll
            for (int e = 0; e < 4; e++) o[mt][nt][e] = 0.f;

    #pragma unroll
    for (int j = 0; j < 4; j++) {
        uint32_t bf[4][2];
        #pragma unroll
        for (int nt = 0; nt < 4; nt++)
            ldsm_x2t(bf[nt], vb + ((j * 16 + (L & 7) + (L >> 3) * 8) * 40 + nt * 8) * 2);
        #pragma unroll
        for (int mt = 0; mt < 2; mt++) {
            uint32_t afr[4];
            afr[0] = packbf(sacc[mt][2 * j    ][0], sacc[mt][2 * j    ][1]);
            afr[1] = packbf(sacc[mt][2 * j    ][2], sacc[mt][2 * j    ][3]);
            afr[2] = packbf(sacc[mt][2 * j + 1][0], sacc[mt][2 * j + 1][1]);
            afr[3] = packbf(sacc[mt][2 * j + 1][2], sacc[mt][2 * j + 1][3]);
            #pragma unroll
            for (int nt = 0; nt < 4; nt++)
                mma16816(o[mt][nt], afr, bf[nt]);
        }
    }

    #pragma unroll
    for (int mt = 0; mt < 2; mt++) {
        int prow = mhalf * 32 + mt * 16 + (lane >> 2);
        #pragma unroll
        for (int nt = 0; nt < 4; nt++) {
            int col = head * 32 + nt * 8 + (lane & 3) * 2;
            __nv_bfloat16* dst = g_attn_bf + (size_t)(tokbase + prow) * CC + col;
            *(__nv_bfloat162*)dst = __floats2bfloat162_rn(o[mt][nt][0], o[mt][nt][1]);
            __nv_bfloat16* dst2 = dst + 8 * CC;
            *(__nv_bfloat162*)dst2 = __floats2bfloat162_rn(o[mt][nt][2], o[mt][nt][3]);
        }
    }
}

// ---------------- HMMA GEMM: block 256(M) x 64(N), BK=32, 8 warps, cp.async 2-stage ----------------
// MODE 0: qkv -> bf16, stride 576, +bias
// MODE 2: mlp1 -> gelu(acc+bias), bf16, stride 768
// MODE 3: mlp2 -> fp32 out = res+acc+bias, stride 192
#define GEMM_SMEM (2*256*40*2 + 2*64*40*2)
template <int MODE>
__global__ __launch_bounds__(256)
void gemm_mma(const __nv_bfloat16* __restrict__ A,
              const __nv_bfloat16* __restrict__ BT,
              const float* __restrict__ bias,
              void* __restrict__ outv,
              const float* __restrict__ res,
              int K) {
    extern __shared__ char gsm[];
    uint32_t sAbase = smem_u32(gsm);             // [2][256][40] bf16
    uint32_t sBbase = sAbase + 40960;            // [2][64][40]  bf16

    int tid  = threadIdx.x;
    int lane = tid & 31;
    int wid  = tid >> 5;
    int wm   = wid & 3;
    int wnw  = wid >> 2;
    int m0 = blockIdx.x * 256;
    int n0 = blockIdx.y * 64;

    float acc[4][4][4];
    #pragma unroll
    for (int i = 0; i < 4; i++)
        #pragma unroll
        for (int j = 0; j < 4; j++)
            #pragma unroll
            for (int k = 0; k < 4; k++) acc[i][j][k] = 0.f;

    const int nch = K >> 5;

    // issue chunk 0 into buffer 0
    {
        #pragma unroll
        for (int i = 0; i < 4; i++) {
            int e = tid + 256 * i; int r = e >> 2, cs = (e & 3) * 8;
            CP16(sAbase + (r * 40 + cs) * 2, A + (size_t)(m0 + r) * K + cs);
        }
        int r = tid >> 2, cs = (tid & 3) * 8;
        CP16(sBbase + (r * 40 + cs) * 2, BT + (size_t)(n0 + r) * K + cs);
        CPCOMMIT();
    }

    for (int c = 0; c < nch; c++) {
        int buf = c & 1;
        if (c + 1 < nch) {
            int nb = buf ^ 1;
            int kc = (c + 1) * 32;
            #pragma unroll
            for (int i = 0; i < 4; i++) {
                int e = tid + 256 * i; int r = e >> 2, cs = (e & 3) * 8;
                CP16(sAbase + nb * 20480 + (r * 40 + cs) * 2,
                     A + (size_t)(m0 + r) * K + kc + cs);
            }
            int r = tid >> 2, cs = (tid & 3) * 8;
            CP16(sBbase + nb * 5120 + (r * 40 + cs) * 2,
                 BT + (size_t)(n0 + r) * K + kc + cs);
            CPCOMMIT();
            CPWAIT1();
        } else {
            CPWAIT0();
        }
        __syncthreads();

        uint32_t sA = sAbase + buf * 20480;
        uint32_t sB = sBbase + buf * 5120;
        #pragma unroll
        for (int ks = 0; ks < 2; ks++) {
            uint32_t a[4][4], b[4][2];
            #pragma unroll
            for (int mt = 0; mt < 4; mt++) {
                uint32_t addr = sA + ((wm * 64 + mt * 16 + (lane & 15)) * 40
                                      + ks * 16 + (lane >> 4) * 8) * 2;
                ldsm_x4(a[mt], addr);
            }
            #pragma unroll
            for (int nt = 0; nt < 4; nt++) {
                uint32_t addr = sB + ((wnw * 32 + nt * 8 + (lane & 7)) * 40
                                      + ks * 16 + ((lane >> 3) & 1) * 8) * 2;
                ldsm_x2(b[nt], addr);
            }
            #pragma unroll
            for (int mt = 0; mt < 4; mt++)
                #pragma unroll
                for (int nt = 0; nt < 4; nt++)
                    mma16816(acc[mt][nt], a[mt], b[nt]);
        }
        __syncthreads();
    }

    // ---------------- epilogue ----------------
    #pragma unroll
    for (int mt = 0; mt < 4; mt++) {
        int rbase = m0 + wm * 64 + mt * 16 + (lane >> 2);
        #pragma unroll
        for (int half = 0; half < 2; half++) {
            int m = rbase + half * 8;
            #pragma unroll
            for (int nt = 0; nt < 4; nt++) {
                int col = n0 + wnw * 32 + nt * 8 + (lane & 3) * 2;
                float v0 = acc[mt][nt][half * 2 + 0] + bias[col];
                float v1 = acc[mt][nt][half * 2 + 1] + bias[col + 1];
                if (MODE == 0) {
                    __nv_bfloat16* o = (__nv_bfloat16*)outv + (size_t)m * 576 + col;
                    *(__nv_bfloat162*)o = __floats2bfloat162_rn(v0, v1);
                } else if (MODE == 2) {
                    v0 = 0.5f * v0 * (1.f + erff(v0 * 0.70710678118654752f));
                    v1 = 0.5f * v1 * (1.f + erff(v1 * 0.70710678118654752f));
                    __nv_bfloat16* o = (__nv_bfloat16*)outv + (size_t)m * 768 + col;
                    *(__nv_bfloat162*)o = __floats2bfloat162_rn(v0, v1);
                } else {
                    float* o = (float*)outv;
                    size_t i0 = (size_t)m * 192 + col;
                    o[i0]     = res[i0]     + v0;
                    o[i0 + 1] = res[i0 + 1] + v1;
                }
            }
        }
    }
}

// ---------------- proj GEMM (128x192 full-width) + un-window + residual + LN2 fused ----------------
// A = g_attn [TOK x 192] (windowed), BT = wprojT [192 x 192]
// writes g_x1 (fp32, pixel layout) and g_h2_bf (bf16 LN2 output, pixel layout)
#define PROJ_SMEM (20480 + 76800 + 4096)
__global__ __launch_bounds__(256)
void gemm_proj_ln(const __nv_bfloat16* __restrict__ A,
                  const __nv_bfloat16* __restrict__ BT,
                  const float* __restrict__ bias,
                  const float* __restrict__ res,
                  float* __restrict__ x1out,
                  const float* __restrict__ g2,
                  const float* __restrict__ b2,
                  __nv_bfloat16* __restrict__ h2out) {
    extern __shared__ char psm[];
    uint32_t sAbase = smem_u32(psm);              // [2][128][40] bf16
    uint32_t sBbase = sAbase + 20480;             // [192][200]   bf16 (whole w_proj)
    float* part = (float*)(psm + 97280);          // [4][128][2]

    int tid  = threadIdx.x;
    int lane = tid & 31;
    int wid  = tid >> 5;
    int wm   = wid & 1;            // 2 warps along M (64 rows each)
    int wnw  = wid >> 1;           // 4 warps along N (48 cols each)
    int m0 = blockIdx.x * 128;
    const int K = 192;
    const int nch = 6;

    // group 0: full B (192x192) + A chunk 0
    for (int i = tid; i < 192 * 24; i += 256) {
        int r = i / 24, c16 = i % 24;
        CP16(sBbase + (r * 200 + c16 * 8) * 2, BT + (size_t)r * 192 + c16 * 8);
    }
    {
        #pragma unroll
        for (int i = 0; i < 2; i++) {
            int e = tid + 256 * i; int r = e >> 2, cs = (e & 3) * 8;
            CP16(sAbase + (r * 40 + cs) * 2, A + (size_t)(m0 + r) * K + cs);
        }
        CPCOMMIT();
    }

    float acc[4][6][4];
    #pragma unroll
    for (int i = 0; i < 4; i++)
        #pragma unroll
        for (int j = 0; j < 6; j++)
            #pragma unroll
            for (int k = 0; k < 4; k++) acc[i][j][k] = 0.f;

    for (int c = 0; c < nch; c++) {
        int buf = c & 1;
        if (c + 1 < nch) {
            int nb = buf ^ 1;
            int kc = (c + 1) * 32;
            #pragma unroll
            for (int i = 0; i < 2; i++) {
                int e = tid + 256 * i; int r = e >> 2, cs = (e & 3) * 8;
                CP16(sAbase + nb * 10240 + (r * 40 + cs) * 2,
                     A + (size_t)(m0 + r) * K + kc + cs);
            }
            CPCOMMIT();
            CPWAIT1();
        } else {
            CPWAIT0();
        }
        __syncthreads();

        uint32_t sA = sAbase + buf * 10240;
        #pragma unroll
        for (int ks = 0; ks < 2; ks++) {
            uint32_t a[4][4], b[6][2];
            #pragma unroll
            for (int mt = 0; mt < 4; mt++) {
                uint32_t addr = sA + ((wm * 64 + mt * 16 + (lane & 15)) * 40
                                      + ks * 16 + (lane >> 4) * 8) * 2;
                ldsm_x4(a[mt], addr);
            }
            #pragma unroll
            for (int nt = 0; nt < 6; nt++) {
                uint32_t addr = sBbase + ((wnw * 48 + nt * 8 + (lane & 7)) * 200
                                          + c * 32 + ks * 16 + ((lane >> 3) & 1) * 8) * 2;
                ldsm_x2(b[nt], addr);
            }
            #pragma unroll
            for (int mt = 0; mt < 4; mt++)
                #pragma unroll
                for (int nt = 0; nt < 6; nt++)
                    mma16816(acc[mt][nt], a[mt], b[nt]);
        }
        __syncthreads();
    }

    // ---- pass 1: x1 = res[pix] + acc + bias; write x1; partial row sums ----
    #pragma unroll
    for (int mt = 0; mt < 4; mt++) {
        #pragma unroll
        for (int half = 0; half < 2; half++) {
            int row = wm * 64 + mt * 16 + (lane >> 2) + half * 8;   // 0..127
            int m = m0 + row;
            int b_ = m >> 12, rem = m & 4095, wnn = rem >> 6, t = rem & 63;
            int y  = (((wnn >> 3) << 3) + (t >> 3) + SH) & 63;
            int xx = (((wnn & 7)  << 3) + (t & 7)  + SH) & 63;
            size_t pixbase = (size_t)(((b_ << 6) + y) * 64 + xx) * CC;
            float s = 0.f, s2 = 0.f;
            #pragma unroll
            for (int nt = 0; nt < 6; nt++) {
                #pragma unroll
                for (int e = 0; e < 2; e++) {
                    int col = wnw * 48 + nt * 8 + (lane & 3) * 2 + e;
                    float v = acc[mt][nt][half * 2 + e] + bias[col] + res[pixbase + col];
                    acc[mt][nt][half * 2 + e] = v;
                    x1out[pixbase + col] = v;
                    s += v; s2 += v * v;
                }
            }
            s  += __shfl_xor_sync(0xffffffffu, s, 1);
            s  += __shfl_xor_sync(0xffffffffu, s, 2);
            s2 += __shfl_xor_sync(0xffffffffu, s2, 1);
            s2 += __shfl_xor_sync(0xffffffffu, s2, 2);
            if ((lane & 3) == 0) {
                part[(wnw * 128 + row) * 2]     = s;
                part[(wnw * 128 + row) * 2 + 1] = s2;
            }
        }
    }
    __syncthreads();

    // ---- pass 2: LN over full 192-col row; write h2 bf16 ----
    #pragma unroll
    for (int mt = 0; mt < 4; mt++) {
        #pragma unroll
        for (int half = 0; half < 2; half++) {
            int row = wm * 64 + mt * 16 + (lane >> 2) + half * 8;
            int m = m0 + row;
            int b_ = m >> 12, rem = m & 4095, wnn = rem >> 6, t = rem & 63;
            int y  = (((wnn >> 3) << 3) + (t >> 3) + SH) & 63;
            int xx = (((wnn & 7)  << 3) + (t & 7)  + SH) & 63;
            size_t pixbase = (size_t)(((b_ << 6) + y) * 64 + xx) * CC;
            float S = 0.f, S2 = 0.f;
            #pragma unroll
            for (int w = 0; w < 4; w++) {
                S  += part[(w * 128 + row) * 2];
                S2 += part[(w * 128 + row) * 2 + 1];
            }
            float mu  = S * (1.f / CC);
            float var = S2 * (1.f / CC) - mu * mu;
            float inv = rsqrtf(var + 1e-5f);
            #pragma unroll
            for (int nt = 0; nt < 6; nt++) {
                int col = wnw * 48 + nt * 8 + (lane & 3) * 2;
                float h0 = (acc[mt][nt][half * 2 + 0] - mu) * inv * g2[col]     + b2[col];
                float h1 = (acc[mt][nt][half * 2 + 1] - mu) * inv * g2[col + 1] + b2[col + 1];
                *(__nv_bfloat162*)(h2out + pixbase + col) = __floats2bfloat162_rn(h0, h1);
            }
        }
    }
}

// ---------------- launch ----------------
extern "C" void kernel_launch(void* const* d_in, const int* in_sizes, int n_in,
                              void* d_out, int out_size) {
    const float* x       = (const float*)d_in[0];
    const float* g1      = (const float*)d_in[1];
    const float* b1      = (const float*)d_in[2];
    const float* w_qkv   = (const float*)d_in[3];
    const float* b_qkv   = (const float*)d_in[4];
    const float* rel_pos = (const float*)d_in[5];
    const float* w_proj  = (const float*)d_in[6];
    const float* b_proj  = (const float*)d_in[7];
    const float* g2      = (const float*)d_in[8];
    const float* b2      = (const float*)d_in[9];
    const float* w_mlp1  = (const float*)d_in[10];
    const float* b_mlp1  = (const float*)d_in[11];
    const float* w_mlp2  = (const float*)d_in[12];
    const float* b_mlp2  = (const float*)d_in[13];
    float* out = (float*)d_out;

    __nv_bfloat16 *p_hwin, *p_qkv, *p_attn, *p_h2, *p_hid;
    __nv_bfloat16 *p_wqkvT, *p_wprojT, *p_wmlp1T, *p_wmlp2T;
    float *p_x1;
    cudaGetSymbolAddress((void**)&p_hwin,   g_hwin_bf);
    cudaGetSymbolAddress((void**)&p_qkv,    g_qkv_bf);
    cudaGetSymbolAddress((void**)&p_attn,   g_attn_bf);
    cudaGetSymbolAddress((void**)&p_x1,     g_x1);
    cudaGetSymbolAddress((void**)&p_h2,     g_h2_bf);
    cudaGetSymbolAddress((void**)&p_hid,    g_hid_bf);
    cudaGetSymbolAddress((void**)&p_wqkvT,  g_wqkvT);
    cudaGetSymbolAddress((void**)&p_wprojT, g_wprojT);
    cudaGetSymbolAddress((void**)&p_wmlp1T, g_wmlp1T);
    cudaGetSymbolAddress((void**)&p_wmlp2T, g_wmlp2T);

    cudaFuncSetAttribute(gemm_mma<0>, cudaFuncAttributeMaxDynamicSharedMemorySize, GEMM_SMEM);
    cudaFuncSetAttribute(gemm_mma<2>, cudaFuncAttributeMaxDynamicSharedMemorySize, GEMM_SMEM);
    cudaFuncSetAttribute(gemm_mma<3>, cudaFuncAttributeMaxDynamicSharedMemorySize, GEMM_SMEM);
    cudaFuncSetAttribute(gemm_proj_ln, cudaFuncAttributeMaxDynamicSharedMemorySize, PROJ_SMEM);
    cudaFuncSetAttribute(attn_mma_kernel, cudaFuncAttributeMaxDynamicSharedMemorySize, AT_SMEM);

    // weight transpose + convert (single launch)
    wconv_all<<<1728, 256>>>(w_qkv, p_wqkvT, w_proj, p_wprojT,
                             w_mlp1, p_wmlp1T, w_mlp2, p_wmlp2T);

    // 1. LN1 + roll + window partition (bf16)
    ln1_window_kernel<<<TOK / 8, 256>>>(x, g1, b1);

    // 2. qkv: [65536,192] @ [192,576] -> bf16
    gemm_mma<0><<<dim3(TOK / 256, 9), 256, GEMM_SMEM>>>(p_hwin, p_wqkvT, b_qkv, p_qkv, nullptr, 192);

    // 3. windowed attention (HMMA)
    attn_mma_kernel<<<BB * NW, 384, AT_SMEM>>>(rel_pos);

    // 4. proj + un-window + residual + LN2 -> g_x1 (fp32) and g_h2 (bf16)
    gemm_proj_ln<<<TOK / 128, 256, PROJ_SMEM>>>(p_attn, p_wprojT, b_proj, x, p_x1, g2, b2, p_h2);

    // 5. mlp1 + gelu: [65536,192] @ [192,768] -> bf16
    gemm_mma<2><<<dim3(TOK / 256, 12), 256, GEMM_SMEM>>>(p_h2, p_wmlp1T, b_mlp1, p_hid, nullptr, 192);

    // 6. mlp2 + residual: [65536,768] @ [768,192] -> fp32 out
    gemm_mma<3><<<dim3(TOK / 256, 3), 256, GEMM_SMEM>>>(p_hid, p_wmlp2T, b_mlp2, out, p_x1, 768);
}